// round 7
// baseline (speedup 1.0000x reference)
#include <cuda_runtime.h>
#include <math.h>

// B=32, J=16, L=4096, MU_P=0.15, MASK_ID=103
#define ROW_LEN   4096
#define THREADS   512
#define EPT       8
#define MASK_ID_F 103.0f
#define FULLMASK  0xFFFFFFFFu

__global__ void __launch_bounds__(THREADS, 4)
gumbel_topk_mask_kernel(const int*   __restrict__ ids,
                        const float* __restrict__ msk2,   // (rows, 2*L)
                        const float* __restrict__ uu,     // (rows, L)
                        float*       __restrict__ out,    // (3, rows, L)
                        int N)
{
    __shared__ unsigned int hist[4][256];   // one per radix pass, cleared once
    __shared__ int          s_warpsum[16];

    const int t    = threadIdx.x;
    const int lane = t & 31;
    const int warp = t >> 5;
    const int row  = blockIdx.x;
    const int base = row * ROW_LEN;          // fits int

    const float* wrow = msk2 + row * (2 * ROW_LEN);
    const float* urow = uu   + base;
    const int*   irow = ids  + base;

    // Clear all 4 histograms once (1024 words, 2 per thread)
    ((unsigned int*)hist)[t]           = 0u;
    ((unsigned int*)hist)[t + THREADS] = 0u;

    // ---- Phase 1: build sortable keys.
    // order(score) == order( max(w,1e-30) / (-log u) ); r>0 so
    // bits(r)|0x80000000 is order-preserving. key==0 marks excluded (w<=0).
    unsigned int mykeys[EPT];
    #pragma unroll
    for (int g = 0; g < 2; g++) {
        float4 w4 = reinterpret_cast<const float4*>(wrow)[t * 2 + g];
        float4 u4 = reinterpret_cast<const float4*>(urow)[t * 2 + g];
        #pragma unroll
        for (int j = 0; j < 4; j++) {
            float w = (j == 0) ? w4.x : (j == 1) ? w4.y : (j == 2) ? w4.z : w4.w;
            float u = (j == 0) ? u4.x : (j == 1) ? u4.y : (j == 2) ? u4.z : u4.w;
            unsigned int key = 0u;
            if (w > 0.0f) {
                float nl = -__logf(u);                        // > 0 (u<1)
                float r  = __fdividef(fmaxf(w, 1e-30f), nl);  // > 0 finite
                key = __float_as_uint(r) | 0x80000000u;
            }
            mykeys[g * 4 + j] = key;
        }
    }
    __syncthreads();   // hist cleared, keys ready

    // ---- Phase 2: 4-pass radix-select; every warp redundantly scans the
    // histogram and derives identical (prefix, kk) — one barrier per pass.
    unsigned int prefixReg = 0u;
    int          kkReg     = 0;

    #pragma unroll
    for (int pass = 0; pass < 4; pass++) {
        const int shift = 24 - 8 * pass;

        if (pass == 0) {
            #pragma unroll
            for (int j = 0; j < EPT; j++) {
                unsigned int key = mykeys[j];
                if (key != 0u) atomicAdd(&hist[0][key >> 24], 1u);
            }
        } else {
            const unsigned int himask = 0xFFFFFFFFu << (shift + 8);
            #pragma unroll
            for (int j = 0; j < EPT; j++) {
                unsigned int key = mykeys[j];
                if ((key & himask) == prefixReg)
                    atomicAdd(&hist[pass][(key >> shift) & 255u], 1u);
            }
        }
        __syncthreads();

        // per-warp scan: lane owns 8 consecutive bins
        unsigned int v[8];
        unsigned int tot = 0u;
        #pragma unroll
        for (int i = 0; i < 8; i++) { v[i] = hist[pass][lane * 8 + i]; tot += v[i]; }

        unsigned int run = tot;                       // inclusive lane-suffix
        #pragma unroll
        for (int off = 1; off < 32; off <<= 1) {
            unsigned int o = __shfl_down_sync(FULLMASK, run, off);
            if (lane + off < 32) run += o;
        }
        unsigned int above = run - tot;               // sum over lanes > lane

        int kkPass;
        if (pass == 0) {
            unsigned int cnt = __shfl_sync(FULLMASK, run, 0);   // total nonzero
            kkPass = (int)floorf(0.15f * (float)cnt);
        } else {
            kkPass = kkReg;
        }

        unsigned int prefNew = 0u;
        int          kkNew   = 0;
        int          found   = 0;
        if (kkPass > 0) {
            unsigned int sufRun = above;
            #pragma unroll
            for (int i = 7; i >= 0; i--) {
                sufRun += v[i];                       // count(byte >= bin i)
                unsigned int cgt = sufRun - v[i];     // count(byte >  bin i)
                if ((int)cgt < kkPass && kkPass <= (int)sufRun) {
                    prefNew = prefixReg | ((unsigned int)(lane * 8 + i) << shift);
                    kkNew   = kkPass - (int)cgt;
                    found   = 1;
                }
            }
        }
        unsigned int fmask = __ballot_sync(FULLMASK, found);
        if (fmask) {
            int src   = __ffs(fmask) - 1;             // exactly one lane finds it
            prefixReg = __shfl_sync(FULLMASK, prefNew, src);
            kkReg     = __shfl_sync(FULLMASK, kkNew,   src);
        } else {                                      // k == 0: select nothing
            prefixReg = 0xFFFFFFFFu;
            kkReg     = 0;
        }
    }

    const unsigned int T = prefixReg;   // k-th largest key (0xFFFFFFFF if k==0)
    const int need_eq    = kkReg;       // # of key==T to take, lowest index first

    // ---- Phase 3: stable tie-break — exclusive scan of (key==T), 1 barrier
    int myEq = 0;
    #pragma unroll
    for (int j = 0; j < EPT; j++) myEq += (mykeys[j] == T) ? 1 : 0;

    int incl = myEq;
    #pragma unroll
    for (int off = 1; off < 32; off <<= 1) {
        int o = __shfl_up_sync(FULLMASK, incl, off);
        if (lane >= off) incl += o;
    }
    if (lane == 31) s_warpsum[warp] = incl;
    __syncthreads();
    int woff = 0;
    #pragma unroll
    for (int w = 0; w < 16; w++)
        woff += (w < warp) ? s_warpsum[w] : 0;
    int running = woff + (incl - myEq);

    // ---- Phase 4: selection + outputs (32-bit addressing)
    float4* o_ids = reinterpret_cast<float4*>(out + base);
    float4* o_m   = reinterpret_cast<float4*>(out + N + base);
    float4* o_nm  = reinterpret_cast<float4*>(out + 2 * N + base);

    #pragma unroll
    for (int g = 0; g < 2; g++) {
        int4 iv4 = reinterpret_cast<const int4*>(irow)[t * 2 + g];
        float oid[4], om[4], onm[4];
        #pragma unroll
        for (int j = 0; j < 4; j++) {
            int iv = (j == 0) ? iv4.x : (j == 1) ? iv4.y : (j == 2) ? iv4.z : iv4.w;
            unsigned int key = mykeys[g * 4 + j];
            bool sel = false;
            if (key > T) sel = true;
            else if (key == T) { sel = (running < need_eq); running++; }
            oid[j] = sel ? MASK_ID_F : (float)iv;
            om[j]  = sel ? 1.0f : 0.0f;
            onm[j] = sel ? -1.0f : -0.0f;
        }
        o_ids[t * 2 + g] = make_float4(oid[0], oid[1], oid[2], oid[3]);
        o_m  [t * 2 + g] = make_float4(om[0],  om[1],  om[2],  om[3]);
        o_nm [t * 2 + g] = make_float4(onm[0], onm[1], onm[2], onm[3]);
    }
}

extern "C" void kernel_launch(void* const* d_in, const int* in_sizes, int n_in,
                              void* d_out, int out_size)
{
    const int*   ids  = (const int*)d_in[0];
    const float* msk2 = (const float*)d_in[1];
    const float* u    = (const float*)d_in[2];
    float*       out  = (float*)d_out;

    const int N    = in_sizes[0];
    const int rows = N / ROW_LEN;

    gumbel_topk_mask_kernel<<<rows, THREADS>>>(ids, msk2, u, out, N);
}

// round 9
// speedup vs baseline: 1.0196x; 1.0196x over previous
#include <cuda_runtime.h>
#include <math.h>

// B=32, J=16, L=4096, MU_P=0.15, MASK_ID=103
#define ROW_LEN   4096
#define THREADS   512
#define EPT       8
#define MASK_ID_F 103.0f
#define FULLMASK  0xFFFFFFFFu

__global__ void __launch_bounds__(THREADS, 4)
gumbel_topk_mask_kernel(const int*   __restrict__ ids,
                        const float* __restrict__ msk2,   // (rows, 2*L)
                        const float* __restrict__ uu,     // (rows, L)
                        float*       __restrict__ out,    // (3, rows, L)
                        int N)
{
    __shared__ __align__(16) int s_ids[ROW_LEN];  // prefetched ids (16KB)
    __shared__ unsigned int hist[4][256];          // one per pass, cleared once
    __shared__ int          s_warpsum[16];
    __shared__ unsigned int s_prefix;
    __shared__ int          s_kk;

    const int t    = threadIdx.x;
    const int lane = t & 31;
    const int warp = t >> 5;
    const int row  = blockIdx.x;
    const int base = row * ROW_LEN;          // fits int

    const float* wrow = msk2 + row * (2 * ROW_LEN);
    const float* urow = uu   + base;
    const int*   irow = ids  + base;

    // Prefetch ids into smem with cp.async (each thread copies its own 32B,
    // and later reads only what it copied -> wait_group 0 is sufficient).
    {
        unsigned long long sdst = __cvta_generic_to_shared(&s_ids[t * EPT]);
        const int* gsrc = irow + t * EPT;
        asm volatile("cp.async.cg.shared.global [%0], [%1], 16;\n"
                     :: "l"(sdst), "l"(gsrc));
        asm volatile("cp.async.cg.shared.global [%0], [%1], 16;\n"
                     :: "l"(sdst + 16), "l"(gsrc + 4));
        asm volatile("cp.async.commit_group;\n");
    }

    // Clear all 4 histograms once (1024 words, 2 per thread)
    ((unsigned int*)hist)[t]           = 0u;
    ((unsigned int*)hist)[t + THREADS] = 0u;

    // ---- Phase 1: build sortable keys.
    // order(score) == order( max(w,1e-30) / (-log u) ); r>0 so
    // bits(r)|0x80000000 is order-preserving. key==0 marks excluded (w<=0).
    unsigned int mykeys[EPT];
    #pragma unroll
    for (int g = 0; g < 2; g++) {
        float4 w4 = reinterpret_cast<const float4*>(wrow)[t * 2 + g];
        float4 u4 = reinterpret_cast<const float4*>(urow)[t * 2 + g];
        #pragma unroll
        for (int j = 0; j < 4; j++) {
            float w = (j == 0) ? w4.x : (j == 1) ? w4.y : (j == 2) ? w4.z : w4.w;
            float u = (j == 0) ? u4.x : (j == 1) ? u4.y : (j == 2) ? u4.z : u4.w;
            unsigned int key = 0u;
            if (w > 0.0f) {
                float nl = -__logf(u);                        // > 0 (u<1)
                float r  = __fdividef(fmaxf(w, 1e-30f), nl);  // > 0 finite
                key = __float_as_uint(r) | 0x80000000u;
            }
            mykeys[g * 4 + j] = key;
        }
    }
    __syncthreads();   // hist cleared, keys ready

    // ---- Phase 2: 4-pass radix-select of k-th largest key
    unsigned int prefixReg = 0u;
    int          kkReg     = 0;

    #pragma unroll
    for (int pass = 0; pass < 4; pass++) {
        const int shift = 24 - 8 * pass;

        if (pass == 0) {
            // Warp-aggregated: valid digits are >=128 (bit31 set); key==0 -> d==0.
            #pragma unroll
            for (int j = 0; j < EPT; j++) {
                unsigned int d = mykeys[j] >> 24;
                unsigned int peers = __match_any_sync(FULLMASK, d);
                if (d != 0u && lane == (unsigned)(__ffs(peers) - 1))
                    atomicAdd(&hist[0][d], (unsigned int)__popc(peers));
            }
        } else {
            #pragma unroll
            for (int j = 0; j < EPT; j++) {
                unsigned int key = mykeys[j];
                if ((key ^ prefixReg) >> (shift + 8) == 0u)
                    atomicAdd(&hist[pass][(key >> shift) & 255u], 1u);
            }
        }
        __syncthreads();

        if (warp == 0) {
            // lane owns 8 consecutive bins; warp-local suffix sums
            unsigned int v[8], lsuf[8];
            #pragma unroll
            for (int i = 0; i < 8; i++) v[i] = hist[pass][lane * 8 + i];
            unsigned int tot = 0u;
            #pragma unroll
            for (int i = 7; i >= 0; i--) { tot += v[i]; lsuf[i] = tot; }

            unsigned int run = tot;
            #pragma unroll
            for (int off = 1; off < 32; off <<= 1) {
                unsigned int o = __shfl_down_sync(FULLMASK, run, off);
                if (lane + off < 32) run += o;
            }
            unsigned int above = run - tot;   // sum over lanes > lane

            int kkPass;
            if (pass == 0) {
                unsigned int cnt = __shfl_sync(FULLMASK, run, 0);   // total nonzero
                kkPass = (int)floorf(0.15f * (float)cnt);
                if (lane == 0 && kkPass <= 0) { s_prefix = 0xFFFFFFFFu; s_kk = 0; }
            } else {
                kkPass = kkReg;
            }

            if (kkPass > 0) {
                #pragma unroll
                for (int i = 0; i < 8; i++) {
                    unsigned int suf = lsuf[i] + above;   // count(byte >= bin)
                    unsigned int cgt = suf - v[i];        // count(byte >  bin)
                    if ((int)cgt < kkPass && kkPass <= (int)suf) {
                        s_prefix = prefixReg | ((unsigned int)(lane * 8 + i) << shift);
                        s_kk     = kkPass - (int)cgt;
                    }
                }
            }
        }
        __syncthreads();
        prefixReg = s_prefix;
        kkReg     = s_kk;
    }

    const unsigned int T = prefixReg;   // k-th largest key (0xFFFFFFFF if k==0)
    const int need_eq    = kkReg;       // # of key==T to take, lowest index first

    // ---- Phase 3: stable tie-break — exclusive scan of (key==T) counts
    int myEq = 0;
    #pragma unroll
    for (int j = 0; j < EPT; j++) myEq += (mykeys[j] == T) ? 1 : 0;

    int incl = myEq;
    #pragma unroll
    for (int off = 1; off < 32; off <<= 1) {
        int o = __shfl_up_sync(FULLMASK, incl, off);
        if (lane >= off) incl += o;
    }
    if (lane == 31) s_warpsum[warp] = incl;
    __syncthreads();
    if (warp == 0 && lane < 16) {
        int v  = s_warpsum[lane];
        int sc = v;
        #pragma unroll
        for (int off = 1; off < 16; off <<= 1) {
            int o = __shfl_up_sync(0x0000FFFFu, sc, off);
            if (lane >= off) sc += o;
        }
        s_warpsum[lane] = sc - v;     // exclusive warp offset
    }
    __syncthreads();
    int running = s_warpsum[warp] + (incl - myEq);

    // ---- Phase 4: selection + outputs (ids from smem prefetch)
    asm volatile("cp.async.wait_group 0;\n");

    float4* o_ids = reinterpret_cast<float4*>(out + base);
    float4* o_m   = reinterpret_cast<float4*>(out + N + base);
    float4* o_nm  = reinterpret_cast<float4*>(out + 2 * N + base);

    #pragma unroll
    for (int g = 0; g < 2; g++) {
        int4 iv4 = reinterpret_cast<const int4*>(&s_ids[t * EPT])[g];
        float oid[4], om[4], onm[4];
        #pragma unroll
        for (int j = 0; j < 4; j++) {
            int iv = (j == 0) ? iv4.x : (j == 1) ? iv4.y : (j == 2) ? iv4.z : iv4.w;
            unsigned int key = mykeys[g * 4 + j];
            bool sel = false;
            if (key > T) sel = true;
            else if (key == T) { sel = (running < need_eq); running++; }
            oid[j] = sel ? MASK_ID_F : (float)iv;
            om[j]  = sel ? 1.0f : 0.0f;
            onm[j] = sel ? -1.0f : -0.0f;
        }
        o_ids[t * 2 + g] = make_float4(oid[0], oid[1], oid[2], oid[3]);
        o_m  [t * 2 + g] = make_float4(om[0],  om[1],  om[2],  om[3]);
        o_nm [t * 2 + g] = make_float4(onm[0], onm[1], onm[2], onm[3]);
    }
}

extern "C" void kernel_launch(void* const* d_in, const int* in_sizes, int n_in,
                              void* d_out, int out_size)
{
    const int*   ids  = (const int*)d_in[0];
    const float* msk2 = (const float*)d_in[1];
    const float* u    = (const float*)d_in[2];
    float*       out  = (float*)d_out;

    const int N    = in_sizes[0];
    const int rows = N / ROW_LEN;

    gumbel_topk_mask_kernel<<<rows, THREADS>>>(ids, msk2, u, out, N);
}

// round 10
// speedup vs baseline: 1.1438x; 1.1218x over previous
#include <cuda_runtime.h>
#include <math.h>

// B=32, J=16, L=4096, MU_P=0.15, MASK_ID=103
#define ROW_LEN   4096
#define THREADS   512
#define EPT       8
#define MASK_ID_F 103.0f
#define FULLMASK  0xFFFFFFFFu
#define HCOPY     16      // one pass-0 histogram copy per warp
#define HSTRIDE   257     // 257 % 32 == 1 -> copy c is skewed by c banks

__global__ void __launch_bounds__(THREADS, 4)
gumbel_topk_mask_kernel(const int*   __restrict__ ids,
                        const float* __restrict__ msk2,   // (rows, 2*L)
                        const float* __restrict__ uu,     // (rows, L)
                        float*       __restrict__ out,    // (3, rows, L)
                        int N)
{
    __shared__ unsigned int wh[HCOPY * HSTRIDE];  // skewed pass-0 copies (~16.1KB)
    __shared__ unsigned int hist[4][256];          // per-pass, cleared once
    __shared__ int          s_warpsum[16];
    __shared__ unsigned int s_prefix;
    __shared__ int          s_kk;

    const int t    = threadIdx.x;
    const int lane = t & 31;
    const int warp = t >> 5;
    const int row  = blockIdx.x;
    const int base = row * ROW_LEN;          // fits int

    const float* wrow = msk2 + row * (2 * ROW_LEN);
    const float* urow = uu   + base;
    const int*   irow = ids  + base;

    // Clear pass-0 warp copies + the 4 shared histograms
    for (int i = t; i < HCOPY * HSTRIDE; i += THREADS) wh[i] = 0u;
    ((unsigned int*)hist)[t]           = 0u;
    ((unsigned int*)hist)[t + THREADS] = 0u;

    // ---- Phase 1: build sortable keys.
    // order(score) == order( max(w,1e-30) / (-log u) ); r>0 so
    // bits(r)|0x80000000 is order-preserving. key==0 marks excluded (w<=0).
    unsigned int mykeys[EPT];
    #pragma unroll
    for (int g = 0; g < 2; g++) {
        float4 w4 = reinterpret_cast<const float4*>(wrow)[t * 2 + g];
        float4 u4 = reinterpret_cast<const float4*>(urow)[t * 2 + g];
        #pragma unroll
        for (int j = 0; j < 4; j++) {
            float w = (j == 0) ? w4.x : (j == 1) ? w4.y : (j == 2) ? w4.z : w4.w;
            float u = (j == 0) ? u4.x : (j == 1) ? u4.y : (j == 2) ? u4.z : u4.w;
            unsigned int key = 0u;
            if (w > 0.0f) {
                float nl = -__logf(u);                        // > 0 (u<1)
                float r  = __fdividef(fmaxf(w, 1e-30f), nl);  // > 0 finite
                key = __float_as_uint(r) | 0x80000000u;
            }
            mykeys[g * 4 + j] = key;
        }
    }
    __syncthreads();   // clears done, keys ready

    // ---- Phase 2: 4-pass radix-select of k-th largest key
    unsigned int prefixReg = 0u;
    int          kkReg     = 0;

    #pragma unroll
    for (int pass = 0; pass < 4; pass++) {
        const int shift = 24 - 8 * pass;

        if (pass == 0) {
            // Privatized + bank-skewed: same digit from different warps hits
            // different banks -> parallel bank units instead of one hot bank.
            const int wb = warp * HSTRIDE;
            #pragma unroll
            for (int j = 0; j < EPT; j++) {
                unsigned int key = mykeys[j];
                if (key != 0u) atomicAdd(&wh[wb + (key >> 24)], 1u);
            }
            __syncthreads();
            if (t < 256) {                       // reduce 16 copies -> hist[0]
                unsigned int s = 0u;
                #pragma unroll
                for (int c = 0; c < HCOPY; c++) s += wh[c * HSTRIDE + t];
                hist[0][t] = s;
            }
        } else {
            #pragma unroll
            for (int j = 0; j < EPT; j++) {
                unsigned int key = mykeys[j];
                if ((key ^ prefixReg) >> (shift + 8) == 0u)
                    atomicAdd(&hist[pass][(key >> shift) & 255u], 1u);
            }
        }
        __syncthreads();

        if (warp == 0) {
            // lane owns 8 consecutive bins; warp-local suffix sums
            unsigned int v[8], lsuf[8];
            #pragma unroll
            for (int i = 0; i < 8; i++) v[i] = hist[pass][lane * 8 + i];
            unsigned int tot = 0u;
            #pragma unroll
            for (int i = 7; i >= 0; i--) { tot += v[i]; lsuf[i] = tot; }

            unsigned int run = tot;
            #pragma unroll
            for (int off = 1; off < 32; off <<= 1) {
                unsigned int o = __shfl_down_sync(FULLMASK, run, off);
                if (lane + off < 32) run += o;
            }
            unsigned int above = run - tot;   // sum over lanes > lane

            int kkPass;
            if (pass == 0) {
                unsigned int cnt = __shfl_sync(FULLMASK, run, 0);   // total nonzero
                kkPass = (int)floorf(0.15f * (float)cnt);
                if (lane == 0 && kkPass <= 0) { s_prefix = 0xFFFFFFFFu; s_kk = 0; }
            } else {
                kkPass = kkReg;
            }

            if (kkPass > 0) {
                #pragma unroll
                for (int i = 0; i < 8; i++) {
                    unsigned int suf = lsuf[i] + above;   // count(byte >= bin)
                    unsigned int cgt = suf - v[i];        // count(byte >  bin)
                    if ((int)cgt < kkPass && kkPass <= (int)suf) {
                        s_prefix = prefixReg | ((unsigned int)(lane * 8 + i) << shift);
                        s_kk     = kkPass - (int)cgt;
                    }
                }
            }
        }
        __syncthreads();
        prefixReg = s_prefix;
        kkReg     = s_kk;
    }

    const unsigned int T = prefixReg;   // k-th largest key (0xFFFFFFFF if k==0)
    const int need_eq    = kkReg;       // # of key==T to take, lowest index first

    // ---- Phase 3: stable tie-break — exclusive scan of (key==T) counts
    int myEq = 0;
    #pragma unroll
    for (int j = 0; j < EPT; j++) myEq += (mykeys[j] == T) ? 1 : 0;

    int incl = myEq;
    #pragma unroll
    for (int off = 1; off < 32; off <<= 1) {
        int o = __shfl_up_sync(FULLMASK, incl, off);
        if (lane >= off) incl += o;
    }
    if (lane == 31) s_warpsum[warp] = incl;
    __syncthreads();
    if (warp == 0 && lane < 16) {
        int v  = s_warpsum[lane];
        int sc = v;
        #pragma unroll
        for (int off = 1; off < 16; off <<= 1) {
            int o = __shfl_up_sync(0x0000FFFFu, sc, off);
            if (lane >= off) sc += o;
        }
        s_warpsum[lane] = sc - v;     // exclusive warp offset
    }
    __syncthreads();
    int running = s_warpsum[warp] + (incl - myEq);

    // ---- Phase 4: selection + outputs (32-bit addressing)
    float4* o_ids = reinterpret_cast<float4*>(out + base);
    float4* o_m   = reinterpret_cast<float4*>(out + N + base);
    float4* o_nm  = reinterpret_cast<float4*>(out + 2 * N + base);

    #pragma unroll
    for (int g = 0; g < 2; g++) {
        int4 iv4 = reinterpret_cast<const int4*>(irow)[t * 2 + g];
        float oid[4], om[4], onm[4];
        #pragma unroll
        for (int j = 0; j < 4; j++) {
            int iv = (j == 0) ? iv4.x : (j == 1) ? iv4.y : (j == 2) ? iv4.z : iv4.w;
            unsigned int key = mykeys[g * 4 + j];
            bool sel = false;
            if (key > T) sel = true;
            else if (key == T) { sel = (running < need_eq); running++; }
            oid[j] = sel ? MASK_ID_F : (float)iv;
            om[j]  = sel ? 1.0f : 0.0f;
            onm[j] = sel ? -1.0f : -0.0f;
        }
        o_ids[t * 2 + g] = make_float4(oid[0], oid[1], oid[2], oid[3]);
        o_m  [t * 2 + g] = make_float4(om[0],  om[1],  om[2],  om[3]);
        o_nm [t * 2 + g] = make_float4(onm[0], onm[1], onm[2], onm[3]);
    }
}

extern "C" void kernel_launch(void* const* d_in, const int* in_sizes, int n_in,
                              void* d_out, int out_size)
{
    const int*   ids  = (const int*)d_in[0];
    const float* msk2 = (const float*)d_in[1];
    const float* u    = (const float*)d_in[2];
    float*       out  = (float*)d_out;

    const int N    = in_sizes[0];
    const int rows = N / ROW_LEN;

    gumbel_topk_mask_kernel<<<rows, THREADS>>>(ids, msk2, u, out, N);
}